// round 2
// baseline (speedup 1.0000x reference)
#include <cuda_runtime.h>
#include <stdint.h>

#define Lq     2048
#define EMB    1024
#define NHEAD  16
#define HD     64

// Scratch (allocation-free rule: device globals)
__device__ float g_Q[Lq * EMB];
__device__ float g_K[Lq * EMB];
__device__ float g_V[Lq * EMB];
__device__ float g_A[Lq * EMB];

// ---------------------------------------------------------------------------
// C[M,N] = A[M,K] @ B[N,K]^T   (both row-major, K contiguous: NT gemm)
// 64x64 tile, BK=16, 256 threads, 4x4 microtile.
// ---------------------------------------------------------------------------
__global__ __launch_bounds__(256)
void gemm_nt_kernel(const float* __restrict__ A, const float* __restrict__ B,
                    float* __restrict__ C, int M, int N, int Kd)
{
    __shared__ float As[16][68];   // [k][m], padded
    __shared__ float Bs[16][68];   // [k][n], padded

    const int tid = threadIdx.x;
    const int tx  = tid & 15;      // n-group
    const int ty  = tid >> 4;      // m-group
    const int bm  = blockIdx.y * 64;
    const int bn  = blockIdx.x * 64;

    const int lm = tid >> 2;           // 0..63
    const int lk = (tid & 3) * 4;      // 0,4,8,12

    float c[4][4] = {};

    for (int k0 = 0; k0 < Kd; k0 += 16) {
        float4 av = *(const float4*)(A + (size_t)(bm + lm) * Kd + k0 + lk);
        float4 bv = *(const float4*)(B + (size_t)(bn + lm) * Kd + k0 + lk);
        As[lk + 0][lm] = av.x; As[lk + 1][lm] = av.y;
        As[lk + 2][lm] = av.z; As[lk + 3][lm] = av.w;
        Bs[lk + 0][lm] = bv.x; Bs[lk + 1][lm] = bv.y;
        Bs[lk + 2][lm] = bv.z; Bs[lk + 3][lm] = bv.w;
        __syncthreads();

        #pragma unroll
        for (int kk = 0; kk < 16; ++kk) {
            float4 a = *(const float4*)&As[kk][ty * 4];
            float4 b = *(const float4*)&Bs[kk][tx * 4];
            c[0][0] += a.x * b.x; c[0][1] += a.x * b.y; c[0][2] += a.x * b.z; c[0][3] += a.x * b.w;
            c[1][0] += a.y * b.x; c[1][1] += a.y * b.y; c[1][2] += a.y * b.z; c[1][3] += a.y * b.w;
            c[2][0] += a.z * b.x; c[2][1] += a.z * b.y; c[2][2] += a.z * b.z; c[2][3] += a.z * b.w;
            c[3][0] += a.w * b.x; c[3][1] += a.w * b.y; c[3][2] += a.w * b.z; c[3][3] += a.w * b.w;
        }
        __syncthreads();
    }

    #pragma unroll
    for (int i = 0; i < 4; ++i) {
        float4 v = make_float4(c[i][0], c[i][1], c[i][2], c[i][3]);
        *(float4*)(C + (size_t)(bm + ty * 4 + i) * N + bn + tx * 4) = v;
    }
}

// ---------------------------------------------------------------------------
// Flash-style masked attention. One thread = one query row (D=64 in regs).
// Block: 128 threads (128 query rows), one head per blockIdx.y.
// K/V staged in 64-key tiles in smem; mask (int32 0/1) tile staged coalesced
// and downconverted to bytes in padded smem.
// Masked keys contribute p = 0 exactly (matches reference's post-softmax
// re-mask; a fully-masked row yields zeros, also matching).
// ---------------------------------------------------------------------------
__global__ __launch_bounds__(128)
void attn_kernel(const float* __restrict__ Q, const float* __restrict__ Kg,
                 const float* __restrict__ Vg, const int* __restrict__ mask,
                 float* __restrict__ O)
{
    __shared__ float   Ks[64 * 64];
    __shared__ float   Vs[64 * 64];
    __shared__ uint8_t Ms[128 * 68];   // padded rows (stride 68)

    const int tid = threadIdx.x;
    const int h   = blockIdx.y;
    const int row = blockIdx.x * 128 + tid;

    // Q row into registers, pre-scaled by 1/sqrt(D)
    float q[64];
    {
        const float4* qsrc = (const float4*)(Q + (size_t)row * EMB + h * HD);
        #pragma unroll
        for (int i = 0; i < 16; ++i) {
            float4 t = qsrc[i];
            q[4 * i + 0] = t.x * 0.125f;
            q[4 * i + 1] = t.y * 0.125f;
            q[4 * i + 2] = t.z * 0.125f;
            q[4 * i + 3] = t.w * 0.125f;
        }
    }

    float acc[64];
    #pragma unroll
    for (int d = 0; d < 64; ++d) acc[d] = 0.f;
    float mval = -3.0e38f;
    float lsum = 0.f;

    // int32 mask base for this (head, query-block)
    const int* mbase = mask + (size_t)h * Lq * Lq + (size_t)blockIdx.x * 128 * Lq;

    for (int kt = 0; kt < Lq / 64; ++kt) {
        // --- stage K and V tiles (64 keys x 64 dims) ---
        #pragma unroll
        for (int i = 0; i < 8; ++i) {
            int idx = i * 128 + tid;
            int r = idx >> 4, c4 = idx & 15;
            ((float4*)Ks)[idx] =
                *(const float4*)(Kg + (size_t)(kt * 64 + r) * EMB + h * HD + c4 * 4);
            ((float4*)Vs)[idx] =
                *(const float4*)(Vg + (size_t)(kt * 64 + r) * EMB + h * HD + c4 * 4);
        }
        // --- stage mask tile: 128 rows x 64 int32, coalesced, to bytes ---
        #pragma unroll
        for (int i = 0; i < 64; ++i) {
            int idx = i * 128 + tid;          // 0 .. 8191
            int r = idx >> 6, c = idx & 63;   // consecutive lanes -> consecutive c
            Ms[r * 68 + c] = (uint8_t)mbase[(size_t)r * Lq + kt * 64 + c];
        }
        __syncthreads();

        const uint8_t* mr = &Ms[tid * 68];

        #pragma unroll 2
        for (int j = 0; j < 64; ++j) {
            const float4* kr = (const float4*)(Ks + j * 64);
            float s0 = 0.f, s1 = 0.f, s2 = 0.f, s3 = 0.f;
            #pragma unroll
            for (int d = 0; d < 16; ++d) {
                float4 kv = kr[d];
                s0 += q[4 * d + 0] * kv.x;
                s1 += q[4 * d + 1] * kv.y;
                s2 += q[4 * d + 2] * kv.z;
                s3 += q[4 * d + 3] * kv.w;
            }
            float s = (s0 + s1) + (s2 + s3);

            float p = 0.f;
            if (!mr[j]) {
                if (s > mval) {               // rare: rescale running state
                    float corr = __expf(mval - s);
                    lsum *= corr;
                    #pragma unroll
                    for (int d = 0; d < 64; ++d) acc[d] *= corr;
                    mval = s;
                }
                p = __expf(s - mval);
                lsum += p;
            }

            const float4* vr = (const float4*)(Vs + j * 64);
            #pragma unroll
            for (int d = 0; d < 16; ++d) {
                float4 vv = vr[d];
                acc[4 * d + 0] += p * vv.x;
                acc[4 * d + 1] += p * vv.y;
                acc[4 * d + 2] += p * vv.z;
                acc[4 * d + 3] += p * vv.w;
            }
        }
        __syncthreads();
    }

    float inv = (lsum > 0.f) ? (1.f / lsum) : 0.f;
    float4* od = (float4*)(O + (size_t)row * EMB + h * HD);
    #pragma unroll
    for (int i = 0; i < 16; ++i)
        od[i] = make_float4(acc[4 * i + 0] * inv, acc[4 * i + 1] * inv,
                            acc[4 * i + 2] * inv, acc[4 * i + 3] * inv);
}

// ---------------------------------------------------------------------------
extern "C" void kernel_launch(void* const* d_in, const int* in_sizes, int n_in,
                              void* d_out, int out_size)
{
    const float* q    = (const float*)d_in[0];
    const float* k    = (const float*)d_in[1];
    const float* v    = (const float*)d_in[2];
    const int*   mask = (const int*)d_in[3];
    const float* Wq   = (const float*)d_in[4];
    const float* Wk   = (const float*)d_in[5];
    const float* Wv   = (const float*)d_in[6];
    const float* Wo   = (const float*)d_in[7];
    float*       out  = (float*)d_out;

    float *gQ, *gK, *gV, *gA;
    cudaGetSymbolAddress((void**)&gQ, g_Q);
    cudaGetSymbolAddress((void**)&gK, g_K);
    cudaGetSymbolAddress((void**)&gV, g_V);
    cudaGetSymbolAddress((void**)&gA, g_A);

    dim3 gblk(256);
    dim3 ggrid(EMB / 64, Lq / 64);   // (N/64, M/64)

    gemm_nt_kernel<<<ggrid, gblk>>>(q, Wq, gQ, Lq, EMB, EMB);
    gemm_nt_kernel<<<ggrid, gblk>>>(k, Wk, gK, Lq, EMB, EMB);
    gemm_nt_kernel<<<ggrid, gblk>>>(v, Wv, gV, Lq, EMB, EMB);

    dim3 agrid(Lq / 128, NHEAD);
    attn_kernel<<<agrid, 128>>>(gQ, gK, gV, mask, gA);

    gemm_nt_kernel<<<ggrid, gblk>>>(gA, Wo, out, Lq, EMB, EMB);
}

// round 3
// speedup vs baseline: 1.0462x; 1.0462x over previous
#include <cuda_runtime.h>
#include <stdint.h>

#define Lq     2048
#define EMB    1024
#define NHEAD  16
#define HD     64

// Scratch (allocation-free rule: device globals)
__device__ float g_Q[Lq * EMB];
__device__ float g_K[Lq * EMB];
__device__ float g_V[Lq * EMB];
__device__ float g_A[Lq * EMB];

// ---------------------------------------------------------------------------
// C[M,N] = A[M,K] @ B[N,K]^T   (both row-major, K contiguous: NT gemm)
// 64x64 tile, BK=16, 256 threads, 4x4 microtile.
// ---------------------------------------------------------------------------
__global__ __launch_bounds__(256)
void gemm_nt_kernel(const float* __restrict__ A, const float* __restrict__ B,
                    float* __restrict__ C, int M, int N, int Kd)
{
    __shared__ float As[16][68];   // [k][m], padded
    __shared__ float Bs[16][68];   // [k][n], padded

    const int tid = threadIdx.x;
    const int tx  = tid & 15;      // n-group
    const int ty  = tid >> 4;      // m-group
    const int bm  = blockIdx.y * 64;
    const int bn  = blockIdx.x * 64;

    const int lm = tid >> 2;           // 0..63
    const int lk = (tid & 3) * 4;      // 0,4,8,12

    float c[4][4] = {};

    for (int k0 = 0; k0 < Kd; k0 += 16) {
        float4 av = *(const float4*)(A + (size_t)(bm + lm) * Kd + k0 + lk);
        float4 bv = *(const float4*)(B + (size_t)(bn + lm) * Kd + k0 + lk);
        As[lk + 0][lm] = av.x; As[lk + 1][lm] = av.y;
        As[lk + 2][lm] = av.z; As[lk + 3][lm] = av.w;
        Bs[lk + 0][lm] = bv.x; Bs[lk + 1][lm] = bv.y;
        Bs[lk + 2][lm] = bv.z; Bs[lk + 3][lm] = bv.w;
        __syncthreads();

        #pragma unroll
        for (int kk = 0; kk < 16; ++kk) {
            float4 a = *(const float4*)&As[kk][ty * 4];
            float4 b = *(const float4*)&Bs[kk][tx * 4];
            c[0][0] += a.x * b.x; c[0][1] += a.x * b.y; c[0][2] += a.x * b.z; c[0][3] += a.x * b.w;
            c[1][0] += a.y * b.x; c[1][1] += a.y * b.y; c[1][2] += a.y * b.z; c[1][3] += a.y * b.w;
            c[2][0] += a.z * b.x; c[2][1] += a.z * b.y; c[2][2] += a.z * b.z; c[2][3] += a.z * b.w;
            c[3][0] += a.w * b.x; c[3][1] += a.w * b.y; c[3][2] += a.w * b.z; c[3][3] += a.w * b.w;
        }
        __syncthreads();
    }

    #pragma unroll
    for (int i = 0; i < 4; ++i) {
        float4 v = make_float4(c[i][0], c[i][1], c[i][2], c[i][3]);
        *(float4*)(C + (size_t)(bm + ty * 4 + i) * N + bn + tx * 4) = v;
    }
}

// ---------------------------------------------------------------------------
// Flash-style masked attention, v2: LANE-PAIR per query row.
// Each thread owns 32 of the 64 head dims; score = partial dot + shfl_xor(1).
// Block: 256 threads = 128 query rows; one head per blockIdx.y.
// K/V staged in 64-key tiles; mask (int32) staged via int4 loads packed to
// bytes. Masked keys contribute p = 0 exactly (matches reference post-softmax
// re-mask; fully-masked rows yield zeros).
// ---------------------------------------------------------------------------
__global__ __launch_bounds__(256, 2)
void attn_kernel(const float* __restrict__ Q, const float* __restrict__ Kg,
                 const float* __restrict__ Vg, const int* __restrict__ mask,
                 float* __restrict__ O)
{
    __shared__ float   Ks[64 * 64];
    __shared__ float   Vs[64 * 64];
    __shared__ uint8_t Ms[128 * 68];   // padded rows (stride 68)

    const int tid  = threadIdx.x;
    const int half = tid & 1;          // which 32-dim half this lane owns
    const int lrow = tid >> 1;         // local query row 0..127
    const int h    = blockIdx.y;
    const int row  = blockIdx.x * 128 + lrow;

    // Q half-row into registers, pre-scaled by 1/sqrt(D)
    float q[32];
    {
        const float4* qsrc =
            (const float4*)(Q + (size_t)row * EMB + h * HD + half * 32);
        #pragma unroll
        for (int i = 0; i < 8; ++i) {
            float4 t = qsrc[i];
            q[4 * i + 0] = t.x * 0.125f;
            q[4 * i + 1] = t.y * 0.125f;
            q[4 * i + 2] = t.z * 0.125f;
            q[4 * i + 3] = t.w * 0.125f;
        }
    }

    float acc[32];
    #pragma unroll
    for (int d = 0; d < 32; ++d) acc[d] = 0.f;
    float mval = -3.0e38f;
    float lsum = 0.f;

    const int* mbase = mask + (size_t)h * Lq * Lq + (size_t)blockIdx.x * 128 * Lq;

    for (int kt = 0; kt < Lq / 64; ++kt) {
        // --- stage K and V tiles (64 keys x 64 dims), 4 float4 each ---
        #pragma unroll
        for (int i = 0; i < 4; ++i) {
            int idx = i * 256 + tid;          // 0..1023
            int r = idx >> 4, c4 = idx & 15;
            ((float4*)Ks)[idx] =
                *(const float4*)(Kg + (size_t)(kt * 64 + r) * EMB + h * HD + c4 * 4);
            ((float4*)Vs)[idx] =
                *(const float4*)(Vg + (size_t)(kt * 64 + r) * EMB + h * HD + c4 * 4);
        }
        // --- stage mask tile: 128 rows x 64 int32 -> packed bytes ---
        #pragma unroll
        for (int i = 0; i < 8; ++i) {
            int idx = i * 256 + tid;          // 0..2047 int4-chunks
            int r = idx >> 4, c4 = idx & 15;  // 16 int4 per row of 64 ints
            int4 mv = *(const int4*)(mbase + (size_t)r * Lq + kt * 64 + c4 * 4);
            uint32_t packed = (uint32_t)(mv.x & 1) | ((uint32_t)(mv.y & 1) << 8) |
                              ((uint32_t)(mv.z & 1) << 16) | ((uint32_t)(mv.w & 1) << 24);
            *(uint32_t*)&Ms[r * 68 + c4 * 4] = packed;
        }
        __syncthreads();

        const uint8_t* mr = &Ms[lrow * 68];

        #pragma unroll 2
        for (int j = 0; j < 64; ++j) {
            const float4* kr = (const float4*)(Ks + j * 64) + half * 8;
            float s0 = 0.f, s1 = 0.f, s2 = 0.f, s3 = 0.f;
            #pragma unroll
            for (int d = 0; d < 8; ++d) {
                float4 kv = kr[d];
                s0 += q[4 * d + 0] * kv.x;
                s1 += q[4 * d + 1] * kv.y;
                s2 += q[4 * d + 2] * kv.z;
                s3 += q[4 * d + 3] * kv.w;
            }
            float s = (s0 + s1) + (s2 + s3);
            s += __shfl_xor_sync(0xffffffffu, s, 1);   // combine halves

            float p = 0.f;
            if (!mr[j]) {
                if (s > mval) {               // rare: rescale running state
                    float corr = __expf(mval - s);
                    lsum *= corr;
                    #pragma unroll
                    for (int d = 0; d < 32; ++d) acc[d] *= corr;
                    mval = s;
                }
                p = __expf(s - mval);
                lsum += p;
            }

            const float4* vr = (const float4*)(Vs + j * 64) + half * 8;
            #pragma unroll
            for (int d = 0; d < 8; ++d) {
                float4 vv = vr[d];
                acc[4 * d + 0] += p * vv.x;
                acc[4 * d + 1] += p * vv.y;
                acc[4 * d + 2] += p * vv.z;
                acc[4 * d + 3] += p * vv.w;
            }
        }
        __syncthreads();
    }

    float inv = (lsum > 0.f) ? (1.f / lsum) : 0.f;
    float4* od = (float4*)(O + (size_t)row * EMB + h * HD + half * 32);
    #pragma unroll
    for (int i = 0; i < 8; ++i)
        od[i] = make_float4(acc[4 * i + 0] * inv, acc[4 * i + 1] * inv,
                            acc[4 * i + 2] * inv, acc[4 * i + 3] * inv);
}

// ---------------------------------------------------------------------------
extern "C" void kernel_launch(void* const* d_in, const int* in_sizes, int n_in,
                              void* d_out, int out_size)
{
    const float* q    = (const float*)d_in[0];
    const float* k    = (const float*)d_in[1];
    const float* v    = (const float*)d_in[2];
    const int*   mask = (const int*)d_in[3];
    const float* Wq   = (const float*)d_in[4];
    const float* Wk   = (const float*)d_in[5];
    const float* Wv   = (const float*)d_in[6];
    const float* Wo   = (const float*)d_in[7];
    float*       out  = (float*)d_out;

    float *gQ, *gK, *gV, *gA;
    cudaGetSymbolAddress((void**)&gQ, g_Q);
    cudaGetSymbolAddress((void**)&gK, g_K);
    cudaGetSymbolAddress((void**)&gV, g_V);
    cudaGetSymbolAddress((void**)&gA, g_A);

    dim3 gblk(256);
    dim3 ggrid(EMB / 64, Lq / 64);   // (N/64, M/64)

    gemm_nt_kernel<<<ggrid, gblk>>>(q, Wq, gQ, Lq, EMB, EMB);
    gemm_nt_kernel<<<ggrid, gblk>>>(k, Wk, gK, Lq, EMB, EMB);
    gemm_nt_kernel<<<ggrid, gblk>>>(v, Wv, gV, Lq, EMB, EMB);

    dim3 agrid(Lq / 128, NHEAD);
    attn_kernel<<<agrid, 256>>>(gQ, gK, gV, mask, gA);

    gemm_nt_kernel<<<ggrid, gblk>>>(gA, Wo, out, Lq, EMB, EMB);
}

// round 5
// speedup vs baseline: 1.1689x; 1.1173x over previous
#include <cuda_runtime.h>
#include <stdint.h>

#define Lq     2048
#define EMB    1024
#define NHEAD  16
#define HD     64

// Scratch (allocation-free rule: device globals)
__device__ float g_Q[Lq * EMB];
__device__ float g_K[Lq * EMB];
__device__ float g_V[Lq * EMB];
__device__ float g_A[Lq * EMB];

__device__ __forceinline__ float to_tf32(float x) {
    float r; asm("cvt.rna.tf32.f32 %0, %1;" : "=f"(r) : "f"(x)); return r;
}

// m16n8k8 tf32 HMMA, D (+)= A*B, row.col
__device__ __forceinline__ void mma_tf32(float d[4], const float a0, const float a1,
                                         const float a2, const float a3,
                                         const float b0, const float b1) {
    asm volatile(
        "mma.sync.aligned.m16n8k8.row.col.f32.tf32.tf32.f32 "
        "{%0,%1,%2,%3}, {%4,%5,%6,%7}, {%8,%9}, {%0,%1,%2,%3};\n"
        : "+f"(d[0]), "+f"(d[1]), "+f"(d[2]), "+f"(d[3])
        : "r"(__float_as_uint(a0)), "r"(__float_as_uint(a1)),
          "r"(__float_as_uint(a2)), "r"(__float_as_uint(a3)),
          "r"(__float_as_uint(b0)), "r"(__float_as_uint(b1)));
}

// ===========================================================================
// Warp-MMA tf32 NT GEMM with 3xTF32 split: C[M,N] = A[M,K] @ B[N,K]^T.
// CTA tile 128x128, 8 warps (2m x 4n), warp tile 64x32, K-chunk 16.
// ===========================================================================
__global__ __launch_bounds__(256, 2)
void gemm_mma_kernel(const float* __restrict__ A, const float* __restrict__ B,
                     float* __restrict__ C)
{
    __shared__ float As_hi[128][20], As_lo[128][20];
    __shared__ float Bs_hi[128][20], Bs_lo[128][20];

    const int tid  = threadIdx.x;
    const int lane = tid & 31;
    const int wid  = tid >> 5;
    const int g    = lane >> 2;     // group id (row within frag)
    const int t4   = lane & 3;      // thread-in-group (col within frag)
    const int wm   = (wid & 1) * 64;     // warp m offset in tile
    const int wn   = (wid >> 1) * 32;    // warp n offset in tile

    const int bm = blockIdx.y * 128;
    const int bn = blockIdx.x * 128;

    float d[4][4][4];               // [mi][ni][reg]
    #pragma unroll
    for (int i = 0; i < 4; ++i)
        #pragma unroll
        for (int j = 0; j < 4; ++j)
            #pragma unroll
            for (int r = 0; r < 4; ++r) d[i][j][r] = 0.f;

    for (int c = 0; c < EMB / 16; ++c) {
        __syncthreads();
        // ---- stage 128x16 chunks of A and B, split hi/lo ----
        #pragma unroll
        for (int j = 0; j < 2; ++j) {
            int idx = j * 256 + tid;        // 0..511
            int r   = idx >> 2;             // row 0..127
            int c4  = idx & 3;              // which float4 of the 16 cols
            float4 av = *(const float4*)(A + (size_t)(bm + r) * EMB + c * 16 + c4 * 4);
            float4 bv = *(const float4*)(B + (size_t)(bn + r) * EMB + c * 16 + c4 * 4);

            float4 ah = make_float4(to_tf32(av.x), to_tf32(av.y), to_tf32(av.z), to_tf32(av.w));
            float4 al = make_float4(to_tf32(av.x - ah.x), to_tf32(av.y - ah.y),
                                    to_tf32(av.z - ah.z), to_tf32(av.w - ah.w));
            float4 bh = make_float4(to_tf32(bv.x), to_tf32(bv.y), to_tf32(bv.z), to_tf32(bv.w));
            float4 bl = make_float4(to_tf32(bv.x - bh.x), to_tf32(bv.y - bh.y),
                                    to_tf32(bv.z - bh.z), to_tf32(bv.w - bh.w));

            *(float4*)&As_hi[r][c4 * 4] = ah;
            *(float4*)&As_lo[r][c4 * 4] = al;
            *(float4*)&Bs_hi[r][c4 * 4] = bh;
            *(float4*)&Bs_lo[r][c4 * 4] = bl;
        }
        __syncthreads();

        // ---- 2 k-steps of 8 ----
        #pragma unroll
        for (int ks = 0; ks < 2; ++ks) {
            const int k0 = ks * 8 + t4;
            // B fragments for all 4 ni
            float bhi[4][2], blo[4][2];
            #pragma unroll
            for (int ni = 0; ni < 4; ++ni) {
                int n = wn + ni * 8 + g;
                bhi[ni][0] = Bs_hi[n][k0];     bhi[ni][1] = Bs_hi[n][k0 + 4];
                blo[ni][0] = Bs_lo[n][k0];     blo[ni][1] = Bs_lo[n][k0 + 4];
            }
            #pragma unroll
            for (int mi = 0; mi < 4; ++mi) {
                int m = wm + mi * 16 + g;
                float ah0 = As_hi[m][k0],     ah1 = As_hi[m + 8][k0];
                float ah2 = As_hi[m][k0 + 4], ah3 = As_hi[m + 8][k0 + 4];
                float al0 = As_lo[m][k0],     al1 = As_lo[m + 8][k0];
                float al2 = As_lo[m][k0 + 4], al3 = As_lo[m + 8][k0 + 4];
                #pragma unroll
                for (int ni = 0; ni < 4; ++ni) {
                    mma_tf32(d[mi][ni], ah0, ah1, ah2, ah3, bhi[ni][0], bhi[ni][1]);
                    mma_tf32(d[mi][ni], ah0, ah1, ah2, ah3, blo[ni][0], blo[ni][1]);
                    mma_tf32(d[mi][ni], al0, al1, al2, al3, bhi[ni][0], bhi[ni][1]);
                }
            }
        }
    }

    // ---- epilogue: D frags -> C ----
    #pragma unroll
    for (int mi = 0; mi < 4; ++mi) {
        int m = bm + wm + mi * 16 + g;
        #pragma unroll
        for (int ni = 0; ni < 4; ++ni) {
            int n = bn + wn + ni * 8 + 2 * t4;
            *(float2*)(C + (size_t)m * EMB + n)       = make_float2(d[mi][ni][0], d[mi][ni][1]);
            *(float2*)(C + (size_t)(m + 8) * EMB + n) = make_float2(d[mi][ni][2], d[mi][ni][3]);
        }
    }
}

// ---------------------------------------------------------------------------
// Flash-style masked attention (unchanged from R3: lane-pair per query row).
// ---------------------------------------------------------------------------
__global__ __launch_bounds__(256, 2)
void attn_kernel(const float* __restrict__ Q, const float* __restrict__ Kg,
                 const float* __restrict__ Vg, const int* __restrict__ mask,
                 float* __restrict__ O)
{
    __shared__ float   Ks[64 * 64];
    __shared__ float   Vs[64 * 64];
    __shared__ uint8_t Ms[128 * 68];

    const int tid  = threadIdx.x;
    const int half = tid & 1;
    const int lrow = tid >> 1;
    const int h    = blockIdx.y;
    const int row  = blockIdx.x * 128 + lrow;

    float q[32];
    {
        const float4* qsrc =
            (const float4*)(Q + (size_t)row * EMB + h * HD + half * 32);
        #pragma unroll
        for (int i = 0; i < 8; ++i) {
            float4 t = qsrc[i];
            q[4 * i + 0] = t.x * 0.125f;
            q[4 * i + 1] = t.y * 0.125f;
            q[4 * i + 2] = t.z * 0.125f;
            q[4 * i + 3] = t.w * 0.125f;
        }
    }

    float acc[32];
    #pragma unroll
    for (int d = 0; d < 32; ++d) acc[d] = 0.f;
    float mval = -3.0e38f;
    float lsum = 0.f;

    const int* mbase = mask + (size_t)h * Lq * Lq + (size_t)blockIdx.x * 128 * Lq;

    for (int kt = 0; kt < Lq / 64; ++kt) {
        #pragma unroll
        for (int i = 0; i < 4; ++i) {
            int idx = i * 256 + tid;
            int r = idx >> 4, c4 = idx & 15;
            ((float4*)Ks)[idx] =
                *(const float4*)(Kg + (size_t)(kt * 64 + r) * EMB + h * HD + c4 * 4);
            ((float4*)Vs)[idx] =
                *(const float4*)(Vg + (size_t)(kt * 64 + r) * EMB + h * HD + c4 * 4);
        }
        #pragma unroll
        for (int i = 0; i < 8; ++i) {
            int idx = i * 256 + tid;
            int r = idx >> 4, c4 = idx & 15;
            int4 mv = *(const int4*)(mbase + (size_t)r * Lq + kt * 64 + c4 * 4);
            uint32_t packed = (uint32_t)(mv.x & 1) | ((uint32_t)(mv.y & 1) << 8) |
                              ((uint32_t)(mv.z & 1) << 16) | ((uint32_t)(mv.w & 1) << 24);
            *(uint32_t*)&Ms[r * 68 + c4 * 4] = packed;
        }
        __syncthreads();

        const uint8_t* mr = &Ms[lrow * 68];

        #pragma unroll 2
        for (int j = 0; j < 64; ++j) {
            const float4* kr = (const float4*)(Ks + j * 64) + half * 8;
            float s0 = 0.f, s1 = 0.f, s2 = 0.f, s3 = 0.f;
            #pragma unroll
            for (int d = 0; d < 8; ++d) {
                float4 kv = kr[d];
                s0 += q[4 * d + 0] * kv.x;
                s1 += q[4 * d + 1] * kv.y;
                s2 += q[4 * d + 2] * kv.z;
                s3 += q[4 * d + 3] * kv.w;
            }
            float s = (s0 + s1) + (s2 + s3);
            s += __shfl_xor_sync(0xffffffffu, s, 1);

            float p = 0.f;
            if (!mr[j]) {
                if (s > mval) {
                    float corr = __expf(mval - s);
                    lsum *= corr;
                    #pragma unroll
                    for (int d = 0; d < 32; ++d) acc[d] *= corr;
                    mval = s;
                }
                p = __expf(s - mval);
                lsum += p;
            }

            const float4* vr = (const float4*)(Vs + j * 64) + half * 8;
            #pragma unroll
            for (int d = 0; d < 8; ++d) {
                float4 vv = vr[d];
                acc[4 * d + 0] += p * vv.x;
                acc[4 * d + 1] += p * vv.y;
                acc[4 * d + 2] += p * vv.z;
                acc[4 * d + 3] += p * vv.w;
            }
        }
        __syncthreads();
    }

    float inv = (lsum > 0.f) ? (1.f / lsum) : 0.f;
    float4* od = (float4*)(O + (size_t)row * EMB + h * HD + half * 32);
    #pragma unroll
    for (int i = 0; i < 8; ++i)
        od[i] = make_float4(acc[4 * i + 0] * inv, acc[4 * i + 1] * inv,
                            acc[4 * i + 2] * inv, acc[4 * i + 3] * inv);
}

// ---------------------------------------------------------------------------
extern "C" void kernel_launch(void* const* d_in, const int* in_sizes, int n_in,
                              void* d_out, int out_size)
{
    const float* q    = (const float*)d_in[0];
    const float* k    = (const float*)d_in[1];
    const float* v    = (const float*)d_in[2];
    const int*   mask = (const int*)d_in[3];
    const float* Wq   = (const float*)d_in[4];
    const float* Wk   = (const float*)d_in[5];
    const float* Wv   = (const float*)d_in[6];
    const float* Wo   = (const float*)d_in[7];
    float*       out  = (float*)d_out;

    float *gQ, *gK, *gV, *gA;
    cudaGetSymbolAddress((void**)&gQ, g_Q);
    cudaGetSymbolAddress((void**)&gK, g_K);
    cudaGetSymbolAddress((void**)&gV, g_V);
    cudaGetSymbolAddress((void**)&gA, g_A);

    dim3 ggrid(EMB / 128, Lq / 128);   // (N/128, M/128) = (8, 16)

    gemm_mma_kernel<<<ggrid, 256>>>(q, Wq, gQ);
    gemm_mma_kernel<<<ggrid, 256>>>(k, Wk, gK);
    gemm_mma_kernel<<<ggrid, 256>>>(v, Wv, gV);

    dim3 agrid(Lq / 128, NHEAD);
    attn_kernel<<<agrid, 256>>>(gQ, gK, gV, mask, gA);

    gemm_mma_kernel<<<ggrid, 256>>>(gA, Wo, out);
}

// round 6
// speedup vs baseline: 2.2718x; 1.9435x over previous
#include <cuda_runtime.h>
#include <stdint.h>

#define Lq     2048
#define EMB    1024
#define NHEAD  16
#define HD     64

// Scratch (allocation-free rule: device globals)
__device__ float g_Q[Lq * EMB];
__device__ float g_K[Lq * EMB];
__device__ float g_V[Lq * EMB];
__device__ float g_A[Lq * EMB];

__device__ __forceinline__ float to_tf32(float x) {
    float r; asm("cvt.rna.tf32.f32 %0, %1;" : "=f"(r) : "f"(x)); return r;
}

// m16n8k8 tf32 HMMA, D (+)= A*B, row.col
__device__ __forceinline__ void mma_tf32(float d[4], const float a0, const float a1,
                                         const float a2, const float a3,
                                         const float b0, const float b1) {
    asm volatile(
        "mma.sync.aligned.m16n8k8.row.col.f32.tf32.tf32.f32 "
        "{%0,%1,%2,%3}, {%4,%5,%6,%7}, {%8,%9}, {%0,%1,%2,%3};\n"
        : "+f"(d[0]), "+f"(d[1]), "+f"(d[2]), "+f"(d[3])
        : "r"(__float_as_uint(a0)), "r"(__float_as_uint(a1)),
          "r"(__float_as_uint(a2)), "r"(__float_as_uint(a3)),
          "r"(__float_as_uint(b0)), "r"(__float_as_uint(b1)));
}

// ===========================================================================
// Warp-MMA tf32 NT GEMM with 3xTF32 split: C[M,N] = A[M,K] @ B[N,K]^T.
// (unchanged from R5 — proven correct)
// ===========================================================================
__global__ __launch_bounds__(256, 2)
void gemm_mma_kernel(const float* __restrict__ A, const float* __restrict__ B,
                     float* __restrict__ C)
{
    __shared__ float As_hi[128][20], As_lo[128][20];
    __shared__ float Bs_hi[128][20], Bs_lo[128][20];

    const int tid  = threadIdx.x;
    const int lane = tid & 31;
    const int wid  = tid >> 5;
    const int g    = lane >> 2;
    const int t4   = lane & 3;
    const int wm   = (wid & 1) * 64;
    const int wn   = (wid >> 1) * 32;

    const int bm = blockIdx.y * 128;
    const int bn = blockIdx.x * 128;

    float d[4][4][4];
    #pragma unroll
    for (int i = 0; i < 4; ++i)
        #pragma unroll
        for (int j = 0; j < 4; ++j)
            #pragma unroll
            for (int r = 0; r < 4; ++r) d[i][j][r] = 0.f;

    for (int c = 0; c < EMB / 16; ++c) {
        __syncthreads();
        #pragma unroll
        for (int j = 0; j < 2; ++j) {
            int idx = j * 256 + tid;
            int r   = idx >> 2;
            int c4  = idx & 3;
            float4 av = *(const float4*)(A + (size_t)(bm + r) * EMB + c * 16 + c4 * 4);
            float4 bv = *(const float4*)(B + (size_t)(bn + r) * EMB + c * 16 + c4 * 4);

            float4 ah = make_float4(to_tf32(av.x), to_tf32(av.y), to_tf32(av.z), to_tf32(av.w));
            float4 al = make_float4(to_tf32(av.x - ah.x), to_tf32(av.y - ah.y),
                                    to_tf32(av.z - ah.z), to_tf32(av.w - ah.w));
            float4 bh = make_float4(to_tf32(bv.x), to_tf32(bv.y), to_tf32(bv.z), to_tf32(bv.w));
            float4 bl = make_float4(to_tf32(bv.x - bh.x), to_tf32(bv.y - bh.y),
                                    to_tf32(bv.z - bh.z), to_tf32(bv.w - bh.w));

            *(float4*)&As_hi[r][c4 * 4] = ah;
            *(float4*)&As_lo[r][c4 * 4] = al;
            *(float4*)&Bs_hi[r][c4 * 4] = bh;
            *(float4*)&Bs_lo[r][c4 * 4] = bl;
        }
        __syncthreads();

        #pragma unroll
        for (int ks = 0; ks < 2; ++ks) {
            const int k0 = ks * 8 + t4;
            float bhi[4][2], blo[4][2];
            #pragma unroll
            for (int ni = 0; ni < 4; ++ni) {
                int n = wn + ni * 8 + g;
                bhi[ni][0] = Bs_hi[n][k0];     bhi[ni][1] = Bs_hi[n][k0 + 4];
                blo[ni][0] = Bs_lo[n][k0];     blo[ni][1] = Bs_lo[n][k0 + 4];
            }
            #pragma unroll
            for (int mi = 0; mi < 4; ++mi) {
                int m = wm + mi * 16 + g;
                float ah0 = As_hi[m][k0],     ah1 = As_hi[m + 8][k0];
                float ah2 = As_hi[m][k0 + 4], ah3 = As_hi[m + 8][k0 + 4];
                float al0 = As_lo[m][k0],     al1 = As_lo[m + 8][k0];
                float al2 = As_lo[m][k0 + 4], al3 = As_lo[m + 8][k0 + 4];
                #pragma unroll
                for (int ni = 0; ni < 4; ++ni) {
                    mma_tf32(d[mi][ni], ah0, ah1, ah2, ah3, bhi[ni][0], bhi[ni][1]);
                    mma_tf32(d[mi][ni], ah0, ah1, ah2, ah3, blo[ni][0], blo[ni][1]);
                    mma_tf32(d[mi][ni], al0, al1, al2, al3, bhi[ni][0], bhi[ni][1]);
                }
            }
        }
    }

    #pragma unroll
    for (int mi = 0; mi < 4; ++mi) {
        int m = bm + wm + mi * 16 + g;
        #pragma unroll
        for (int ni = 0; ni < 4; ++ni) {
            int n = bn + wn + ni * 8 + 2 * t4;
            *(float2*)(C + (size_t)m * EMB + n)       = make_float2(d[mi][ni][0], d[mi][ni][1]);
            *(float2*)(C + (size_t)(m + 8) * EMB + n) = make_float2(d[mi][ni][2], d[mi][ni][3]);
        }
    }
}

// ===========================================================================
// Tensor-core flash attention.
// CTA = (query block of 128, head). 8 warps; warp w owns queries 16w..16w+15.
// Per 64-key tile: S = Q·K^T (3xTF32), online softmax with bit-packed mask,
// P·V (plain tf32). Q frags register-resident for the whole kernel.
// Smem: Kh[64][76], Kl[64][76], Vs[64][72], Mk[128][2] (u32 mask bits).
// ===========================================================================
#define KP 76
#define VP 72
#define OFF_KH 0
#define OFF_KL 19456
#define OFF_VS 38912
#define OFF_MK 57344
#define ATTN_SMEM 58368

__global__ __launch_bounds__(256, 1)
void attn_mma_kernel(const float* __restrict__ Q, const float* __restrict__ Kg,
                     const float* __restrict__ Vg, const int* __restrict__ mask,
                     float* __restrict__ O)
{
    extern __shared__ char smem[];
    float*    Kh = (float*)(smem + OFF_KH);
    float*    Kl = (float*)(smem + OFF_KL);
    float*    Vs = (float*)(smem + OFF_VS);
    uint32_t* Mk = (uint32_t*)(smem + OFF_MK);

    const int tid  = threadIdx.x;
    const int lane = tid & 31;
    const int wid  = tid >> 5;
    const int g    = lane >> 2;
    const int t4   = lane & 3;
    const int h    = blockIdx.y;
    const int qb   = blockIdx.x;
    const int hb   = h * HD;
    const int row0 = qb * 128 + wid * 16;

    // ---- Q fragments: scaled by 1/8, split hi/lo, resident all kernel ----
    float qh[8][4], ql[8][4];
    #pragma unroll
    for (int ks = 0; ks < 8; ++ks) {
        int d0 = hb + 8 * ks + t4;
        float v0 = Q[(size_t)(row0 + g)     * EMB + d0]     * 0.125f;
        float v1 = Q[(size_t)(row0 + g + 8) * EMB + d0]     * 0.125f;
        float v2 = Q[(size_t)(row0 + g)     * EMB + d0 + 4] * 0.125f;
        float v3 = Q[(size_t)(row0 + g + 8) * EMB + d0 + 4] * 0.125f;
        qh[ks][0] = to_tf32(v0); ql[ks][0] = to_tf32(v0 - qh[ks][0]);
        qh[ks][1] = to_tf32(v1); ql[ks][1] = to_tf32(v1 - qh[ks][1]);
        qh[ks][2] = to_tf32(v2); ql[ks][2] = to_tf32(v2 - qh[ks][2]);
        qh[ks][3] = to_tf32(v3); ql[ks][3] = to_tf32(v3 - qh[ks][3]);
    }

    float o[8][4];
    #pragma unroll
    for (int ni = 0; ni < 8; ++ni)
        #pragma unroll
        for (int r = 0; r < 4; ++r) o[ni][r] = 0.f;
    float m0 = -1.0e30f, m1 = -1.0e30f;
    float l0 = 0.f, l1 = 0.f;

    const int key_stage = tid >> 2;      // 0..63
    const int qq        = tid & 3;       // 0..3
    const int mrow      = tid >> 1;      // 0..127
    const int mhf       = tid & 1;       // 0..1

    for (int kt = 0; kt < Lq / 64; ++kt) {
        // ================= staging =================
        {
            const float* ksrc = Kg + (size_t)(kt * 64 + key_stage) * EMB + hb;
            #pragma unroll
            for (int kk = 0; kk < 2; ++kk) {
                int ks = qq + kk * 4;
                float4 x0 = *(const float4*)(ksrc + 8 * ks);
                float4 x1 = *(const float4*)(ksrc + 8 * ks + 4);
                float4 h0 = make_float4(to_tf32(x0.x), to_tf32(x0.y), to_tf32(x0.z), to_tf32(x0.w));
                float4 l0v = make_float4(to_tf32(x0.x - h0.x), to_tf32(x0.y - h0.y),
                                         to_tf32(x0.z - h0.z), to_tf32(x0.w - h0.w));
                float4 h1 = make_float4(to_tf32(x1.x), to_tf32(x1.y), to_tf32(x1.z), to_tf32(x1.w));
                float4 l1v = make_float4(to_tf32(x1.x - h1.x), to_tf32(x1.y - h1.y),
                                         to_tf32(x1.z - h1.z), to_tf32(x1.w - h1.w));
                *(float4*)(Kh + key_stage * KP + 8 * ks)     = h0;
                *(float4*)(Kh + key_stage * KP + 8 * ks + 4) = h1;
                *(float4*)(Kl + key_stage * KP + 8 * ks)     = l0v;
                *(float4*)(Kl + key_stage * KP + 8 * ks + 4) = l1v;
            }
            const float* vsrc = Vg + (size_t)(kt * 64 + key_stage) * EMB + hb;
            #pragma unroll
            for (int i = 0; i < 4; ++i) {
                float4 x = *(const float4*)(vsrc + qq * 16 + i * 4);
                float4 t = make_float4(to_tf32(x.x), to_tf32(x.y), to_tf32(x.z), to_tf32(x.w));
                *(float4*)(Vs + key_stage * VP + qq * 16 + i * 4) = t;
            }
            const int* mb = mask + (size_t)h * Lq * Lq +
                            (size_t)(qb * 128 + mrow) * Lq + kt * 64 + mhf * 32;
            uint32_t bits = 0;
            #pragma unroll
            for (int i = 0; i < 8; ++i) {
                int4 mv = *(const int4*)(mb + i * 4);
                bits |= (uint32_t)(mv.x != 0) << (i * 4 + 0);
                bits |= (uint32_t)(mv.y != 0) << (i * 4 + 1);
                bits |= (uint32_t)(mv.z != 0) << (i * 4 + 2);
                bits |= (uint32_t)(mv.w != 0) << (i * 4 + 3);
            }
            Mk[mrow * 2 + mhf] = bits;
        }
        __syncthreads();

        // ================= S = Q K^T (3xTF32) =================
        float s[8][4];
        #pragma unroll
        for (int ni = 0; ni < 8; ++ni)
            #pragma unroll
            for (int r = 0; r < 4; ++r) s[ni][r] = 0.f;

        #pragma unroll
        for (int ks = 0; ks < 8; ++ks) {
            #pragma unroll
            for (int ni = 0; ni < 8; ++ni) {
                const float* kr = Kh + (8 * ni + g) * KP + 8 * ks + t4;
                const float* lr = Kl + (8 * ni + g) * KP + 8 * ks + t4;
                float b0h = kr[0], b1h = kr[4];
                float b0l = lr[0], b1l = lr[4];
                mma_tf32(s[ni], qh[ks][0], qh[ks][1], qh[ks][2], qh[ks][3], b0h, b1h);
                mma_tf32(s[ni], qh[ks][0], qh[ks][1], qh[ks][2], qh[ks][3], b0l, b1l);
                mma_tf32(s[ni], ql[ks][0], ql[ks][1], ql[ks][2], ql[ks][3], b0h, b1h);
            }
        }

        // ================= masked online softmax =================
        const int rbase = wid * 16 + g;
        uint32_t w0lo = Mk[rbase * 2],        w0hi = Mk[rbase * 2 + 1];
        uint32_t w1lo = Mk[(rbase + 8) * 2],  w1hi = Mk[(rbase + 8) * 2 + 1];

        float tm0 = -1.0e30f, tm1 = -1.0e30f;
        #pragma unroll
        for (int ni = 0; ni < 8; ++ni) {
            uint32_t wr0 = (ni < 4) ? w0lo : w0hi;
            uint32_t wr1 = (ni < 4) ? w1lo : w1hi;
            int b = 8 * (ni & 3) + 2 * t4;
            tm0 = fmaxf(tm0, ((wr0 >> b) & 1u)       ? -1.0e30f : s[ni][0]);
            tm0 = fmaxf(tm0, ((wr0 >> (b + 1)) & 1u) ? -1.0e30f : s[ni][1]);
            tm1 = fmaxf(tm1, ((wr1 >> b) & 1u)       ? -1.0e30f : s[ni][2]);
            tm1 = fmaxf(tm1, ((wr1 >> (b + 1)) & 1u) ? -1.0e30f : s[ni][3]);
        }
        tm0 = fmaxf(tm0, __shfl_xor_sync(0xffffffffu, tm0, 1));
        tm0 = fmaxf(tm0, __shfl_xor_sync(0xffffffffu, tm0, 2));
        tm1 = fmaxf(tm1, __shfl_xor_sync(0xffffffffu, tm1, 1));
        tm1 = fmaxf(tm1, __shfl_xor_sync(0xffffffffu, tm1, 2));

        float mn0 = fmaxf(m0, tm0), mn1 = fmaxf(m1, tm1);
        float c0 = __expf(m0 - mn0), c1 = __expf(m1 - mn1);
        m0 = mn0; m1 = mn1;

        float rs0 = 0.f, rs1 = 0.f;
        #pragma unroll
        for (int ni = 0; ni < 8; ++ni) {
            uint32_t wr0 = (ni < 4) ? w0lo : w0hi;
            uint32_t wr1 = (ni < 4) ? w1lo : w1hi;
            int b = 8 * (ni & 3) + 2 * t4;
            float p0 = ((wr0 >> b) & 1u)       ? 0.f : __expf(s[ni][0] - mn0);
            float p1 = ((wr0 >> (b + 1)) & 1u) ? 0.f : __expf(s[ni][1] - mn0);
            float p2 = ((wr1 >> b) & 1u)       ? 0.f : __expf(s[ni][2] - mn1);
            float p3 = ((wr1 >> (b + 1)) & 1u) ? 0.f : __expf(s[ni][3] - mn1);
            s[ni][0] = p0; s[ni][1] = p1; s[ni][2] = p2; s[ni][3] = p3;
            rs0 += p0 + p1; rs1 += p2 + p3;
        }
        rs0 += __shfl_xor_sync(0xffffffffu, rs0, 1);
        rs0 += __shfl_xor_sync(0xffffffffu, rs0, 2);
        rs1 += __shfl_xor_sync(0xffffffffu, rs1, 1);
        rs1 += __shfl_xor_sync(0xffffffffu, rs1, 2);
        l0 = l0 * c0 + rs0;
        l1 = l1 * c1 + rs1;

        #pragma unroll
        for (int ni = 0; ni < 8; ++ni) {
            o[ni][0] *= c0; o[ni][1] *= c0;
            o[ni][2] *= c1; o[ni][3] *= c1;
        }

        // ================= O += P V (tf32) =================
        const int srcA = g * 4 + (t4 >> 1);
        const int srcB = srcA + 2;
        const int par  = t4 & 1;
        #pragma unroll
        for (int ki = 0; ki < 8; ++ki) {
            float e0 = __shfl_sync(0xffffffffu, s[ki][0], srcA);
            float o0 = __shfl_sync(0xffffffffu, s[ki][1], srcA);
            float e2 = __shfl_sync(0xffffffffu, s[ki][0], srcB);
            float o2 = __shfl_sync(0xffffffffu, s[ki][1], srcB);
            float e1 = __shfl_sync(0xffffffffu, s[ki][2], srcA);
            float o1 = __shfl_sync(0xffffffffu, s[ki][3], srcA);
            float e3 = __shfl_sync(0xffffffffu, s[ki][2], srcB);
            float o3 = __shfl_sync(0xffffffffu, s[ki][3], srcB);
            float a0 = to_tf32(par ? o0 : e0);
            float a1 = to_tf32(par ? o1 : e1);
            float a2 = to_tf32(par ? o2 : e2);
            float a3 = to_tf32(par ? o3 : e3);
            const float* v0 = Vs + (8 * ki + t4) * VP + g;
            const float* v1 = Vs + (8 * ki + t4 + 4) * VP + g;
            #pragma unroll
            for (int ni = 0; ni < 8; ++ni) {
                mma_tf32(o[ni], a0, a1, a2, a3, v0[8 * ni], v1[8 * ni]);
            }
        }
        __syncthreads();
    }

    // ================= epilogue =================
    float inv0 = (l0 > 0.f) ? (1.f / l0) : 0.f;
    float inv1 = (l1 > 0.f) ? (1.f / l1) : 0.f;
    #pragma unroll
    for (int ni = 0; ni < 8; ++ni) {
        int col = hb + 8 * ni + 2 * t4;
        *(float2*)(O + (size_t)(row0 + g)     * EMB + col) =
            make_float2(o[ni][0] * inv0, o[ni][1] * inv0);
        *(float2*)(O + (size_t)(row0 + g + 8) * EMB + col) =
            make_float2(o[ni][2] * inv1, o[ni][3] * inv1);
    }
}

// ---------------------------------------------------------------------------
extern "C" void kernel_launch(void* const* d_in, const int* in_sizes, int n_in,
                              void* d_out, int out_size)
{
    const float* q    = (const float*)d_in[0];
    const float* k    = (const float*)d_in[1];
    const float* v    = (const float*)d_in[2];
    const int*   mask = (const int*)d_in[3];
    const float* Wq   = (const float*)d_in[4];
    const float* Wk   = (const float*)d_in[5];
    const float* Wv   = (const float*)d_in[6];
    const float* Wo   = (const float*)d_in[7];
    float*       out  = (float*)d_out;

    float *gQ, *gK, *gV, *gA;
    cudaGetSymbolAddress((void**)&gQ, g_Q);
    cudaGetSymbolAddress((void**)&gK, g_K);
    cudaGetSymbolAddress((void**)&gV, g_V);
    cudaGetSymbolAddress((void**)&gA, g_A);

    cudaFuncSetAttribute(attn_mma_kernel,
                         cudaFuncAttributeMaxDynamicSharedMemorySize, ATTN_SMEM);

    dim3 ggrid(EMB / 128, Lq / 128);   // (8, 16)

    gemm_mma_kernel<<<ggrid, 256>>>(q, Wq, gQ);
    gemm_mma_kernel<<<ggrid, 256>>>(k, Wk, gK);
    gemm_mma_kernel<<<ggrid, 256>>>(v, Wv, gV);

    dim3 agrid(Lq / 128, NHEAD);       // (16, 16)
    attn_mma_kernel<<<agrid, 256, ATTN_SMEM>>>(gQ, gK, gV, mask, gA);

    gemm_mma_kernel<<<ggrid, 256>>>(gA, Wo, out);
}